// round 12
// baseline (speedup 1.0000x reference)
#include <cuda_runtime.h>
#include <cuda_bf16.h>
#include <math.h>
#include <cstdint>

#define NN 100000
#define NE 1600000
#define RR 4
#define DD 128
#define CC 2
#define NR (NN * RR)                     // 400000 segments
#define SCAN_NBLK ((NR + 1023) / 1024)   // 391

// ---- scratch (device globals: no allocation allowed in kernel_launch) ----
__device__ float g_h1[(size_t)NN * DD];        // 51.2 MB
__device__ float g_h2[(size_t)NN * DD];        // 51.2 MB
__device__ float g_xw3[(size_t)RR * NN * CC];  // 3.2 MB
__device__ int   g_cnt[NR];
__device__ float g_inv[NR];
__device__ int   g_off[NR + 1];
__device__ int   g_cur[NR];
__device__ int   g_bsum[512];
__device__ int   g_boff[512];
__device__ unsigned g_csr[NE];
// aggregated means, pre-split bf16 hi/lo: layout [seg][128], seg = n*RR + r
__device__ __align__(16) __nv_bfloat16 g_ahi[(size_t)NR * DD];   // 102.4 MB
__device__ __align__(16) __nv_bfloat16 g_alo[(size_t)NR * DD];   // 102.4 MB
__device__ __align__(16) __nv_bfloat16 g_whi[2 * RR * DD * DD];
__device__ __align__(16) __nv_bfloat16 g_wlo[2 * RR * DD * DD];

__device__ __forceinline__ uint32_t smem_u32(const void* p) {
    uint32_t a;
    asm("{ .reg .u64 t; cvta.to.shared.u64 t, %1; cvt.u32.u64 %0, t; }" : "=r"(a) : "l"(p));
    return a;
}

// ------------------------------------------------------------------ utils
__global__ void zero_i_kernel(int* p, int n) {
    int i = blockIdx.x * blockDim.x + threadIdx.x;
    if (i < n) p[i] = 0;
}
__global__ void count_kernel(const int* __restrict__ ei, const int* __restrict__ et) {
    int e = blockIdx.x * blockDim.x + threadIdx.x;
    if (e < NE) atomicAdd(&g_cnt[ei[NE + e] * RR + et[e]], 1);
}
__global__ void inv_kernel() {      // also zeroes the placement cursors
    int i = blockIdx.x * blockDim.x + threadIdx.x;
    if (i < NR) {
        g_inv[i] = 1.0f / fmaxf((float)g_cnt[i], 1.0f);
        g_cur[i] = 0;
    }
}

// ---------------------------------------------- CSR build: scan + placement
__global__ void k_blocksum() {
    __shared__ int sh[256];
    int b = blockIdx.x, t = threadIdx.x;
    int base = b * 1024 + t * 4;
    int s = 0;
#pragma unroll
    for (int j = 0; j < 4; j++) {
        int idx = base + j;
        if (idx < NR) s += g_cnt[idx];
    }
    sh[t] = s;
    __syncthreads();
    for (int o = 128; o > 0; o >>= 1) {
        if (t < o) sh[t] += sh[t + o];
        __syncthreads();
    }
    if (t == 0) g_bsum[b] = sh[0];
}
__global__ void k_scanb(int nb) {
    if (threadIdx.x == 0) {
        int run = 0;
        for (int i = 0; i < nb; i++) { g_boff[i] = run; run += g_bsum[i]; }
        g_off[NR] = run;
    }
}
__global__ void k_scanlocal() {
    __shared__ int sh[256];
    int b = blockIdx.x, t = threadIdx.x;
    int base = b * 1024 + t * 4;
    int c[4], s = 0;
#pragma unroll
    for (int j = 0; j < 4; j++) {
        int idx = base + j;
        c[j] = (idx < NR) ? g_cnt[idx] : 0;
        s += c[j];
    }
    sh[t] = s;
    __syncthreads();
    for (int o = 1; o < 256; o <<= 1) {
        int u = (t >= o) ? sh[t - o] : 0;
        __syncthreads();
        sh[t] += u;
        __syncthreads();
    }
    int run = g_boff[b] + sh[t] - s;
#pragma unroll
    for (int j = 0; j < 4; j++) {
        int idx = base + j;
        if (idx < NR) { g_off[idx] = run; run += c[j]; }
    }
}
__global__ void place_kernel(const int* __restrict__ ei, const int* __restrict__ et) {
    int e = blockIdx.x * blockDim.x + threadIdx.x;
    if (e >= NE) return;
    int src = ei[e], d = ei[NE + e], r = et[e];
    int seg = d * RR + r;
    int pos = g_off[seg] + atomicAdd(&g_cur[seg], 1);
    g_csr[pos] = (unsigned)src;
}

// W [R,K,N] fp32 -> transposed bf16 splits at [layer][r][n][k]
__global__ void convert_w_kernel(const float* __restrict__ W, int layer) {
    int i = blockIdx.x * blockDim.x + threadIdx.x;
    if (i >= RR * DD * DD) return;
    int r = i / (DD * DD), rem = i % (DD * DD);
    int n = rem / DD, k = rem % DD;
    float v = W[(r * DD + k) * DD + n];
    __nv_bfloat16 hi = __float2bfloat16_rn(v);
    __nv_bfloat16 lo = __float2bfloat16_rn(v - __bfloat162float(hi));
    g_whi[layer * RR * DD * DD + i] = hi;
    g_wlo[layer * RR * DD * DD + i] = lo;
}

// ------------------------------------- gather-mean (round-6 proven version)
// one warp per dst node; A[n*RR+r][:] = inv * sum(x[src]); split to bf16 hi/lo
__global__ void __launch_bounds__(256) gather_kernel(const float* __restrict__ X) {
    int gw = (blockIdx.x * blockDim.x + threadIdx.x) >> 5;
    int lane = threadIdx.x & 31;
    if (gw >= NN) return;
    const float4* x4 = reinterpret_cast<const float4*>(X);

#pragma unroll
    for (int r = 0; r < RR; r++) {
        int seg = gw * RR + r;
        int s = g_off[seg], e = g_off[seg + 1];
        float4 a0 = make_float4(0.f, 0.f, 0.f, 0.f);
        float4 a1 = make_float4(0.f, 0.f, 0.f, 0.f);
        int j = s;
        for (; j + 1 < e; j += 2) {
            float4 v0 = x4[(size_t)g_csr[j] * 32 + lane];
            float4 v1 = x4[(size_t)g_csr[j + 1] * 32 + lane];
            a0.x += v0.x; a0.y += v0.y; a0.z += v0.z; a0.w += v0.w;
            a1.x += v1.x; a1.y += v1.y; a1.z += v1.z; a1.w += v1.w;
        }
        if (j < e) {
            float4 v0 = x4[(size_t)g_csr[j] * 32 + lane];
            a0.x += v0.x; a0.y += v0.y; a0.z += v0.z; a0.w += v0.w;
        }
        float iv = g_inv[seg];
        float m0 = (a0.x + a1.x) * iv, m1 = (a0.y + a1.y) * iv;
        float m2 = (a0.z + a1.z) * iv, m3 = (a0.w + a1.w) * iv;
        __nv_bfloat16 h0 = __float2bfloat16_rn(m0);
        __nv_bfloat16 h1 = __float2bfloat16_rn(m1);
        __nv_bfloat16 h2 = __float2bfloat16_rn(m2);
        __nv_bfloat16 h3 = __float2bfloat16_rn(m3);
        __nv_bfloat16 l0 = __float2bfloat16_rn(m0 - __bfloat162float(h0));
        __nv_bfloat16 l1 = __float2bfloat16_rn(m1 - __bfloat162float(h1));
        __nv_bfloat16 l2 = __float2bfloat16_rn(m2 - __bfloat162float(h2));
        __nv_bfloat16 l3 = __float2bfloat16_rn(m3 - __bfloat162float(h3));
        uint2 hp, lp;
        hp.x = ((uint32_t)__bfloat16_as_ushort(h1) << 16) | __bfloat16_as_ushort(h0);
        hp.y = ((uint32_t)__bfloat16_as_ushort(h3) << 16) | __bfloat16_as_ushort(h2);
        lp.x = ((uint32_t)__bfloat16_as_ushort(l1) << 16) | __bfloat16_as_ushort(l0);
        lp.y = ((uint32_t)__bfloat16_as_ushort(l3) << 16) | __bfloat16_as_ushort(l2);
        size_t base = (size_t)seg * DD + lane * 4;
        *reinterpret_cast<uint2*>(g_ahi + base) = hp;
        *reinterpret_cast<uint2*>(g_alo + base) = lp;
    }
}

// ------------------------------------------- GEMM: h = tanh(sum_r A_r @ W_r)
// TM=64 nodes x 128 cols per CTA, 104.4 KB smem -> 2 CTAs/SM (load/MMA interleave
// across co-resident CTAs). 8 warps: 2 (m) x 4 (n), warp tile 32x32.
#define SB 272                           // padded row stride in bytes (136 bf16)
#define ATILE (64 * SB)                  // 17408
#define WTILE (128 * SB)                 // 34816
#define OFF_A_HI 0
#define OFF_A_LO ATILE
#define OFF_W_HI (2 * ATILE)
#define OFF_W_LO (2 * ATILE + WTILE)
#define GEMM_SMEM (2 * ATILE + 2 * WTILE)   // 104448

__global__ void __launch_bounds__(256, 2) gemm_kernel(int layer, float* __restrict__ OUT) {
    extern __shared__ char smem[];
    const uint32_t sbase = smem_u32(smem);
    const int tid = threadIdx.x;
    const int wid = tid >> 5, lane = tid & 31;
    const int n0 = blockIdx.x * 64;

    const int wm = (wid & 1) * 32;
    const int wn = (wid >> 1) * 32;

    float acc[2][4][4];
#pragma unroll
    for (int mi = 0; mi < 2; mi++)
#pragma unroll
        for (int ni = 0; ni < 4; ni++)
#pragma unroll
            for (int q = 0; q < 4; q++) acc[mi][ni][q] = 0.0f;

    const int a_row = (lane & 15);
    const int a_kof = (lane >> 4) * 8;
    const int b_row = ((lane >> 4) << 3) + (lane & 7);
    const int b_kof = ((lane >> 3) & 1) * 8;

    for (int r = 0; r < RR; r++) {
        __syncthreads();   // previous iteration's smem reads done
        // A tile: 64 rows x 256 B
        for (int u = tid; u < 1024; u += 256) {
            int row = u >> 4, col = (u & 15) * 8;
            uint32_t off = (uint32_t)(row * SB + col * 2);
            uint4 vh = make_uint4(0, 0, 0, 0), vl = make_uint4(0, 0, 0, 0);
            int n = n0 + row;
            if (n < NN) {
                size_t ab = ((size_t)n * RR + r) * DD + col;
                vh = *reinterpret_cast<const uint4*>(g_ahi + ab);
                vl = *reinterpret_cast<const uint4*>(g_alo + ab);
            }
            *reinterpret_cast<uint4*>(smem + OFF_A_HI + off) = vh;
            *reinterpret_cast<uint4*>(smem + OFF_A_LO + off) = vl;
        }
        // W tile: 128 rows x 256 B (L2-hot)
        const __nv_bfloat16* wh = g_whi + ((size_t)layer * RR + r) * DD * DD;
        const __nv_bfloat16* wl = g_wlo + ((size_t)layer * RR + r) * DD * DD;
        for (int u = tid; u < 2048; u += 256) {
            int row = u >> 4, col = (u & 15) * 8;
            uint32_t off = (uint32_t)(row * SB + col * 2);
            *reinterpret_cast<uint4*>(smem + OFF_W_HI + off) =
                *reinterpret_cast<const uint4*>(wh + (size_t)row * DD + col);
            *reinterpret_cast<uint4*>(smem + OFF_W_LO + off) =
                *reinterpret_cast<const uint4*>(wl + (size_t)row * DD + col);
        }
        __syncthreads();

#pragma unroll
        for (int pass = 0; pass < 3; pass++) {
            const uint32_t aB = sbase + ((pass == 2) ? OFF_A_LO : OFF_A_HI);
            const uint32_t bB = sbase + ((pass == 1) ? OFF_W_LO : OFF_W_HI);
#pragma unroll
            for (int ks = 0; ks < 8; ks++) {
                const int k0 = ks * 16;
                uint32_t a[2][4];
#pragma unroll
                for (int mi = 0; mi < 2; mi++) {
                    uint32_t addr = aB + (uint32_t)((wm + mi * 16 + a_row) * SB +
                                                    (k0 + a_kof) * 2);
                    asm volatile("ldmatrix.sync.aligned.m8n8.x4.shared.b16 {%0,%1,%2,%3}, [%4];"
                                 : "=r"(a[mi][0]), "=r"(a[mi][1]), "=r"(a[mi][2]), "=r"(a[mi][3])
                                 : "r"(addr));
                }
                uint32_t b[2][4];
#pragma unroll
                for (int nb = 0; nb < 2; nb++) {
                    uint32_t addr = bB + (uint32_t)((wn + nb * 16 + b_row) * SB +
                                                    (k0 + b_kof) * 2);
                    asm volatile("ldmatrix.sync.aligned.m8n8.x4.shared.b16 {%0,%1,%2,%3}, [%4];"
                                 : "=r"(b[nb][0]), "=r"(b[nb][1]), "=r"(b[nb][2]), "=r"(b[nb][3])
                                 : "r"(addr));
                }
#pragma unroll
                for (int mi = 0; mi < 2; mi++) {
#pragma unroll
                    for (int ni = 0; ni < 4; ni++) {
                        uint32_t b0 = b[ni >> 1][(ni & 1) ? 2 : 0];
                        uint32_t b1 = b[ni >> 1][(ni & 1) ? 3 : 1];
                        asm volatile(
                            "mma.sync.aligned.m16n8k16.row.col.f32.bf16.bf16.f32 "
                            "{%0,%1,%2,%3}, {%4,%5,%6,%7}, {%8,%9}, {%0,%1,%2,%3};"
                            : "+f"(acc[mi][ni][0]), "+f"(acc[mi][ni][1]),
                              "+f"(acc[mi][ni][2]), "+f"(acc[mi][ni][3])
                            : "r"(a[mi][0]), "r"(a[mi][1]), "r"(a[mi][2]), "r"(a[mi][3]),
                              "r"(b0), "r"(b1));
                    }
                }
            }
        }
    }

    // ---- epilogue: tanh + write fp32 ----
    const int gid = lane >> 2, tq = lane & 3;
#pragma unroll
    for (int mi = 0; mi < 2; mi++) {
        int row0 = n0 + wm + mi * 16 + gid;
        int row1 = row0 + 8;
#pragma unroll
        for (int ni = 0; ni < 4; ni++) {
            int col = wn + ni * 8 + tq * 2;
            if (row0 < NN)
                *reinterpret_cast<float2*>(OUT + (size_t)row0 * DD + col) =
                    make_float2(tanhf(acc[mi][ni][0]), tanhf(acc[mi][ni][1]));
            if (row1 < NN)
                *reinterpret_cast<float2*>(OUT + (size_t)row1 * DD + col) =
                    make_float2(tanhf(acc[mi][ni][2]), tanhf(acc[mi][ni][3]));
        }
    }
}

// ---------------------------------------------- layer 3 transform (out cols = 2)
__global__ void transform3_kernel(const float* __restrict__ H, const float* __restrict__ W3) {
    __shared__ float hs[32 * DD];
    __shared__ float ws[RR * DD * CC];
    const int t  = threadIdx.x;  // 128
    const int n0 = blockIdx.x * 32;

    for (int i = t; i < RR * DD * CC; i += 128) ws[i] = W3[i];
    for (int i = t; i < 32 * DD; i += 128) {
        int row = i >> 7, col = i & 127;
        int n = n0 + row;
        hs[i] = (n < NN) ? H[(size_t)n * DD + col] : 0.0f;
    }
    __syncthreads();

    for (int o = t; o < 32 * RR * CC; o += 128) {
        int node = o >> 3, rc = o & 7;
        int r = rc >> 1, c = rc & 1;
        float acc = 0.0f;
#pragma unroll 8
        for (int k = 0; k < DD; k++)
            acc = fmaf(hs[node * DD + k], ws[(r * DD + k) * CC + c], acc);
        int n = n0 + node;
        if (n < NN) g_xw3[((size_t)r * NN + n) * CC + c] = acc;
    }
}

// ------------------ fused final: CSR gather of logits + softmax (atomic-free)
__global__ void __launch_bounds__(256) final_kernel(float* __restrict__ out, int out_size) {
    int gw = (blockIdx.x * blockDim.x + threadIdx.x) >> 5;   // node
    int lane = threadIdx.x & 31;
    if (gw >= NN) return;

    float sx = 0.f, sy = 0.f;
#pragma unroll
    for (int r = 0; r < RR; r++) {
        int seg = gw * RR + r;
        int s = g_off[seg], e = g_off[seg + 1];
        float px = 0.f, py = 0.f;
        for (int j = s + lane; j < e; j += 32) {
            unsigned src = g_csr[j];
            float2 v = *reinterpret_cast<const float2*>(&g_xw3[((size_t)r * NN + src) * CC]);
            px += v.x; py += v.y;
        }
        float iv = g_inv[seg];
        sx += px * iv;
        sy += py * iv;
    }
#pragma unroll
    for (int o = 16; o > 0; o >>= 1) {
        sx += __shfl_xor_sync(0xffffffffu, sx, o);
        sy += __shfl_xor_sync(0xffffffffu, sy, o);
    }
    if (lane == 0) {
        float m = fmaxf(sx, sy);
        float ea = __expf(sx - m), eb = __expf(sy - m);
        float inv = 1.0f / (ea + eb);
        *reinterpret_cast<float2*>(out + (size_t)gw * 2) = make_float2(ea * inv, eb * inv);
        if (out_size >= 2 * NN * CC)
            *reinterpret_cast<float2*>(out + (size_t)NN * CC + (size_t)gw * 2) =
                make_float2(sx, sy);
    }
}

// ------------------------------------------------------------------ launch
extern "C" void kernel_launch(void* const* d_in, const int* in_sizes, int n_in,
                              void* d_out, int out_size) {
    const float* x  = (const float*)d_in[0];
    const int*   ei = (const int*)d_in[1];
    const int*   et = (const int*)d_in[2];
    const float* W1 = (const float*)d_in[3];
    const float* W2 = (const float*)d_in[4];
    const float* W3 = (const float*)d_in[5];
    float* out = (float*)d_out;

    static int attr_set = 0;
    if (!attr_set) {
        cudaFuncSetAttribute(gemm_kernel,
                             cudaFuncAttributeMaxDynamicSharedMemorySize, GEMM_SMEM);
        attr_set = 1;
    }

    float *p_h1, *p_h2;
    int* p_cnt;
    cudaGetSymbolAddress((void**)&p_h1, g_h1);
    cudaGetSymbolAddress((void**)&p_h2, g_h2);
    cudaGetSymbolAddress((void**)&p_cnt, g_cnt);

    const int gemm_grid = (NN + 63) / 64;               // 1563
    const int gath_grid = (NN * 32 + 255) / 256;        // 12500

    // counts -> inv(+cursor zero), CSR offsets + placement
    zero_i_kernel<<<(NR + 255) / 256, 256>>>(p_cnt, NR);
    count_kernel<<<(NE + 255) / 256, 256>>>(ei, et);
    inv_kernel<<<(NR + 255) / 256, 256>>>();
    k_blocksum<<<SCAN_NBLK, 256>>>();
    k_scanb<<<1, 32>>>(SCAN_NBLK);
    k_scanlocal<<<SCAN_NBLK, 256>>>();
    place_kernel<<<(NE + 255) / 256, 256>>>(ei, et);

    // weight splits
    convert_w_kernel<<<(RR * DD * DD + 255) / 256, 256>>>(W1, 0);
    convert_w_kernel<<<(RR * DD * DD + 255) / 256, 256>>>(W2, 1);

    // layer 1
    gather_kernel<<<gath_grid, 256>>>(x);
    gemm_kernel<<<gemm_grid, 256, GEMM_SMEM>>>(0, p_h1);

    // layer 2
    gather_kernel<<<gath_grid, 256>>>(p_h1);
    gemm_kernel<<<gemm_grid, 256, GEMM_SMEM>>>(1, p_h2);

    // layer 3: tiny transform then fused CSR-mean + softmax
    transform3_kernel<<<(NN + 31) / 32, 128>>>(p_h2, W3);
    final_kernel<<<gath_grid, 256>>>(out, out_size);
}

// round 13
// speedup vs baseline: 1.0075x; 1.0075x over previous
#include <cuda_runtime.h>
#include <cuda_bf16.h>
#include <math.h>
#include <cstdint>

#define NN 100000
#define NE 1600000
#define RR 4
#define DD 128
#define CC 2
#define NR (NN * RR)                     // 400000 segments
#define SCAN_NBLK ((NR + 1023) / 1024)   // 391

// ---- scratch (device globals: no allocation allowed in kernel_launch) ----
__device__ float g_h1[(size_t)NN * DD];        // 51.2 MB
__device__ float g_h2[(size_t)NN * DD];        // 51.2 MB
__device__ float g_xw3[(size_t)RR * NN * CC];  // 3.2 MB
__device__ int   g_cnt[NR];
__device__ float g_inv[NR];
__device__ int   g_off[NR + 1];
__device__ int   g_cur[NR];
__device__ int   g_bsum[512];
__device__ int   g_boff[512];
__device__ unsigned g_csr[NE];
// aggregated means, pre-split bf16 hi/lo: layout [seg][128], seg = n*RR + r
__device__ __align__(16) __nv_bfloat16 g_ahi[(size_t)NR * DD];   // 102.4 MB
__device__ __align__(16) __nv_bfloat16 g_alo[(size_t)NR * DD];   // 102.4 MB
__device__ __align__(16) __nv_bfloat16 g_whi[2 * RR * DD * DD];
__device__ __align__(16) __nv_bfloat16 g_wlo[2 * RR * DD * DD];

__device__ __forceinline__ uint32_t smem_u32(const void* p) {
    uint32_t a;
    asm("{ .reg .u64 t; cvta.to.shared.u64 t, %1; cvt.u32.u64 %0, t; }" : "=r"(a) : "l"(p));
    return a;
}

// ------------------------------------------------------------------ utils
__global__ void zero_i_kernel(int* p, int n) {
    int i = blockIdx.x * blockDim.x + threadIdx.x;
    if (i < n) p[i] = 0;
}
__global__ void count_kernel(const int* __restrict__ ei, const int* __restrict__ et) {
    int e = blockIdx.x * blockDim.x + threadIdx.x;
    if (e < NE) atomicAdd(&g_cnt[ei[NE + e] * RR + et[e]], 1);
}
__global__ void inv_kernel() {      // also zeroes the placement cursors
    int i = blockIdx.x * blockDim.x + threadIdx.x;
    if (i < NR) {
        g_inv[i] = 1.0f / fmaxf((float)g_cnt[i], 1.0f);
        g_cur[i] = 0;
    }
}

// ---------------------------------------------- CSR build: scan + placement
__global__ void k_blocksum() {
    __shared__ int sh[256];
    int b = blockIdx.x, t = threadIdx.x;
    int base = b * 1024 + t * 4;
    int s = 0;
#pragma unroll
    for (int j = 0; j < 4; j++) {
        int idx = base + j;
        if (idx < NR) s += g_cnt[idx];
    }
    sh[t] = s;
    __syncthreads();
    for (int o = 128; o > 0; o >>= 1) {
        if (t < o) sh[t] += sh[t + o];
        __syncthreads();
    }
    if (t == 0) g_bsum[b] = sh[0];
}
__global__ void k_scanb(int nb) {
    if (threadIdx.x == 0) {
        int run = 0;
        for (int i = 0; i < nb; i++) { g_boff[i] = run; run += g_bsum[i]; }
        g_off[NR] = run;
    }
}
__global__ void k_scanlocal() {
    __shared__ int sh[256];
    int b = blockIdx.x, t = threadIdx.x;
    int base = b * 1024 + t * 4;
    int c[4], s = 0;
#pragma unroll
    for (int j = 0; j < 4; j++) {
        int idx = base + j;
        c[j] = (idx < NR) ? g_cnt[idx] : 0;
        s += c[j];
    }
    sh[t] = s;
    __syncthreads();
    for (int o = 1; o < 256; o <<= 1) {
        int u = (t >= o) ? sh[t - o] : 0;
        __syncthreads();
        sh[t] += u;
        __syncthreads();
    }
    int run = g_boff[b] + sh[t] - s;
#pragma unroll
    for (int j = 0; j < 4; j++) {
        int idx = base + j;
        if (idx < NR) { g_off[idx] = run; run += c[j]; }
    }
}
__global__ void place_kernel(const int* __restrict__ ei, const int* __restrict__ et) {
    int e = blockIdx.x * blockDim.x + threadIdx.x;
    if (e >= NE) return;
    int src = ei[e], d = ei[NE + e], r = et[e];
    int seg = d * RR + r;
    int pos = g_off[seg] + atomicAdd(&g_cur[seg], 1);
    g_csr[pos] = (unsigned)src;
}

// W [R,K,N] fp32 -> transposed bf16 splits at [layer][r][n][k]
__global__ void convert_w_kernel(const float* __restrict__ W, int layer) {
    int i = blockIdx.x * blockDim.x + threadIdx.x;
    if (i >= RR * DD * DD) return;
    int r = i / (DD * DD), rem = i % (DD * DD);
    int n = rem / DD, k = rem % DD;
    float v = W[(r * DD + k) * DD + n];
    __nv_bfloat16 hi = __float2bfloat16_rn(v);
    __nv_bfloat16 lo = __float2bfloat16_rn(v - __bfloat162float(hi));
    g_whi[layer * RR * DD * DD + i] = hi;
    g_wlo[layer * RR * DD * DD + i] = lo;
}

// ------------------------------------- gather-mean (round-6 proven version)
// one warp per dst node; A[n*RR+r][:] = inv * sum(x[src]); split to bf16 hi/lo
__global__ void __launch_bounds__(256) gather_kernel(const float* __restrict__ X) {
    int gw = (blockIdx.x * blockDim.x + threadIdx.x) >> 5;
    int lane = threadIdx.x & 31;
    if (gw >= NN) return;
    const float4* x4 = reinterpret_cast<const float4*>(X);

#pragma unroll
    for (int r = 0; r < RR; r++) {
        int seg = gw * RR + r;
        int s = g_off[seg], e = g_off[seg + 1];
        float4 a0 = make_float4(0.f, 0.f, 0.f, 0.f);
        float4 a1 = make_float4(0.f, 0.f, 0.f, 0.f);
        int j = s;
        for (; j + 1 < e; j += 2) {
            float4 v0 = x4[(size_t)g_csr[j] * 32 + lane];
            float4 v1 = x4[(size_t)g_csr[j + 1] * 32 + lane];
            a0.x += v0.x; a0.y += v0.y; a0.z += v0.z; a0.w += v0.w;
            a1.x += v1.x; a1.y += v1.y; a1.z += v1.z; a1.w += v1.w;
        }
        if (j < e) {
            float4 v0 = x4[(size_t)g_csr[j] * 32 + lane];
            a0.x += v0.x; a0.y += v0.y; a0.z += v0.z; a0.w += v0.w;
        }
        float iv = g_inv[seg];
        float m0 = (a0.x + a1.x) * iv, m1 = (a0.y + a1.y) * iv;
        float m2 = (a0.z + a1.z) * iv, m3 = (a0.w + a1.w) * iv;
        __nv_bfloat16 h0 = __float2bfloat16_rn(m0);
        __nv_bfloat16 h1 = __float2bfloat16_rn(m1);
        __nv_bfloat16 h2 = __float2bfloat16_rn(m2);
        __nv_bfloat16 h3 = __float2bfloat16_rn(m3);
        __nv_bfloat16 l0 = __float2bfloat16_rn(m0 - __bfloat162float(h0));
        __nv_bfloat16 l1 = __float2bfloat16_rn(m1 - __bfloat162float(h1));
        __nv_bfloat16 l2 = __float2bfloat16_rn(m2 - __bfloat162float(h2));
        __nv_bfloat16 l3 = __float2bfloat16_rn(m3 - __bfloat162float(h3));
        uint2 hp, lp;
        hp.x = ((uint32_t)__bfloat16_as_ushort(h1) << 16) | __bfloat16_as_ushort(h0);
        hp.y = ((uint32_t)__bfloat16_as_ushort(h3) << 16) | __bfloat16_as_ushort(h2);
        lp.x = ((uint32_t)__bfloat16_as_ushort(l1) << 16) | __bfloat16_as_ushort(l0);
        lp.y = ((uint32_t)__bfloat16_as_ushort(l3) << 16) | __bfloat16_as_ushort(l2);
        size_t base = (size_t)seg * DD + lane * 4;
        *reinterpret_cast<uint2*>(g_ahi + base) = hp;
        *reinterpret_cast<uint2*>(g_alo + base) = lp;
    }
}

// ------------------------------------------- GEMM (round-6 proven version)
// h = tanh(sum_r A_r @ W_r); 128x128 tile per CTA, 8 warps at 64x32.
#define TPAD 136
#define TBYTES (128 * TPAD * 2)        // 34816

__global__ void __launch_bounds__(256, 1) gemm_kernel(int layer, float* __restrict__ OUT) {
    extern __shared__ char smem[];
    const uint32_t sbase = smem_u32(smem);
    const int tid = threadIdx.x;
    const int wid = tid >> 5, lane = tid & 31;
    const int n0 = blockIdx.x * 128;

    const uint32_t A_HI = 0, A_LO = TBYTES, B_HI = 2 * TBYTES, B_LO = 3 * TBYTES;

    const int wm = (wid & 1) * 64;
    const int wn = (wid >> 1) * 32;

    float acc[4][4][4];
#pragma unroll
    for (int mi = 0; mi < 4; mi++)
#pragma unroll
        for (int ni = 0; ni < 4; ni++)
#pragma unroll
            for (int q = 0; q < 4; q++) acc[mi][ni][q] = 0.0f;

    const int a_row = (lane & 15);
    const int a_kof = (lane >> 4) * 8;
    const int b_row = ((lane >> 4) << 3) + (lane & 7);
    const int b_kof = ((lane >> 3) & 1) * 8;

    for (int r = 0; r < RR; r++) {
        __syncthreads();   // protect previous iteration's smem reads
        // ---- load tiles ----
        const __nv_bfloat16* wh = g_whi + ((size_t)layer * RR + r) * DD * DD;
        const __nv_bfloat16* wl = g_wlo + ((size_t)layer * RR + r) * DD * DD;
        for (int u = tid; u < 2048; u += 256) {
            int row = u >> 4;
            int col = (u & 15) * 8;
            uint32_t off = (uint32_t)(row * (TPAD * 2) + col * 2);
            uint4 vh = make_uint4(0, 0, 0, 0), vl = make_uint4(0, 0, 0, 0);
            int n = n0 + row;
            if (n < NN) {
                size_t ab = ((size_t)n * RR + r) * DD + col;
                vh = *reinterpret_cast<const uint4*>(g_ahi + ab);
                vl = *reinterpret_cast<const uint4*>(g_alo + ab);
            }
            *reinterpret_cast<uint4*>(smem + A_HI + off) = vh;
            *reinterpret_cast<uint4*>(smem + A_LO + off) = vl;
            *reinterpret_cast<uint4*>(smem + B_HI + off) =
                *reinterpret_cast<const uint4*>(wh + (size_t)row * DD + col);
            *reinterpret_cast<uint4*>(smem + B_LO + off) =
                *reinterpret_cast<const uint4*>(wl + (size_t)row * DD + col);
        }
        __syncthreads();

        // ---- 3-product split MMA ----
#pragma unroll
        for (int pass = 0; pass < 3; pass++) {
            const uint32_t aB = sbase + ((pass == 2) ? A_LO : A_HI);
            const uint32_t bB = sbase + ((pass == 1) ? B_LO : B_HI);
#pragma unroll
            for (int ks = 0; ks < 8; ks++) {
                const int k0 = ks * 16;
                uint32_t a[4][4];
#pragma unroll
                for (int mi = 0; mi < 4; mi++) {
                    uint32_t addr = aB + (uint32_t)((wm + mi * 16 + a_row) * (TPAD * 2) +
                                                    (k0 + a_kof) * 2);
                    asm volatile("ldmatrix.sync.aligned.m8n8.x4.shared.b16 {%0,%1,%2,%3}, [%4];"
                                 : "=r"(a[mi][0]), "=r"(a[mi][1]), "=r"(a[mi][2]), "=r"(a[mi][3])
                                 : "r"(addr));
                }
                uint32_t b[2][4];
#pragma unroll
                for (int nb = 0; nb < 2; nb++) {
                    uint32_t addr = bB + (uint32_t)((wn + nb * 16 + b_row) * (TPAD * 2) +
                                                    (k0 + b_kof) * 2);
                    asm volatile("ldmatrix.sync.aligned.m8n8.x4.shared.b16 {%0,%1,%2,%3}, [%4];"
                                 : "=r"(b[nb][0]), "=r"(b[nb][1]), "=r"(b[nb][2]), "=r"(b[nb][3])
                                 : "r"(addr));
                }
#pragma unroll
                for (int mi = 0; mi < 4; mi++) {
#pragma unroll
                    for (int ni = 0; ni < 4; ni++) {
                        uint32_t b0 = b[ni >> 1][(ni & 1) ? 2 : 0];
                        uint32_t b1 = b[ni >> 1][(ni & 1) ? 3 : 1];
                        asm volatile(
                            "mma.sync.aligned.m16n8k16.row.col.f32.bf16.bf16.f32 "
                            "{%0,%1,%2,%3}, {%4,%5,%6,%7}, {%8,%9}, {%0,%1,%2,%3};"
                            : "+f"(acc[mi][ni][0]), "+f"(acc[mi][ni][1]),
                              "+f"(acc[mi][ni][2]), "+f"(acc[mi][ni][3])
                            : "r"(a[mi][0]), "r"(a[mi][1]), "r"(a[mi][2]), "r"(a[mi][3]),
                              "r"(b0), "r"(b1));
                    }
                }
            }
        }
    }

    // ---- epilogue: tanh + write fp32 ----
    const int gid = lane >> 2, tq = lane & 3;
#pragma unroll
    for (int mi = 0; mi < 4; mi++) {
        int row0 = n0 + wm + mi * 16 + gid;
        int row1 = row0 + 8;
#pragma unroll
        for (int ni = 0; ni < 4; ni++) {
            int col = wn + ni * 8 + tq * 2;
            if (row0 < NN)
                *reinterpret_cast<float2*>(OUT + (size_t)row0 * DD + col) =
                    make_float2(tanhf(acc[mi][ni][0]), tanhf(acc[mi][ni][1]));
            if (row1 < NN)
                *reinterpret_cast<float2*>(OUT + (size_t)row1 * DD + col) =
                    make_float2(tanhf(acc[mi][ni][2]), tanhf(acc[mi][ni][3]));
        }
    }
}

// ---------------------------------------------- layer 3 transform (out cols = 2)
__global__ void transform3_kernel(const float* __restrict__ H, const float* __restrict__ W3) {
    __shared__ float hs[32 * DD];
    __shared__ float ws[RR * DD * CC];
    const int t  = threadIdx.x;  // 128
    const int n0 = blockIdx.x * 32;

    for (int i = t; i < RR * DD * CC; i += 128) ws[i] = W3[i];
    for (int i = t; i < 32 * DD; i += 128) {
        int row = i >> 7, col = i & 127;
        int n = n0 + row;
        hs[i] = (n < NN) ? H[(size_t)n * DD + col] : 0.0f;
    }
    __syncthreads();

    for (int o = t; o < 32 * RR * CC; o += 128) {
        int node = o >> 3, rc = o & 7;
        int r = rc >> 1, c = rc & 1;
        float acc = 0.0f;
#pragma unroll 8
        for (int k = 0; k < DD; k++)
            acc = fmaf(hs[node * DD + k], ws[(r * DD + k) * CC + c], acc);
        int n = n0 + node;
        if (n < NN) g_xw3[((size_t)r * NN + n) * CC + c] = acc;
    }
}

// ------------------ fused final: CSR gather of logits + softmax (atomic-free)
__global__ void __launch_bounds__(256) final_kernel(float* __restrict__ out, int out_size) {
    int gw = (blockIdx.x * blockDim.x + threadIdx.x) >> 5;   // node
    int lane = threadIdx.x & 31;
    if (gw >= NN) return;

    float sx = 0.f, sy = 0.f;
#pragma unroll
    for (int r = 0; r < RR; r++) {
        int seg = gw * RR + r;
        int s = g_off[seg], e = g_off[seg + 1];
        float px = 0.f, py = 0.f;
        for (int j = s + lane; j < e; j += 32) {
            unsigned src = g_csr[j];
            float2 v = *reinterpret_cast<const float2*>(&g_xw3[((size_t)r * NN + src) * CC]);
            px += v.x; py += v.y;
        }
        float iv = g_inv[seg];
        sx += px * iv;
        sy += py * iv;
    }
#pragma unroll
    for (int o = 16; o > 0; o >>= 1) {
        sx += __shfl_xor_sync(0xffffffffu, sx, o);
        sy += __shfl_xor_sync(0xffffffffu, sy, o);
    }
    if (lane == 0) {
        float m = fmaxf(sx, sy);
        float ea = __expf(sx - m), eb = __expf(sy - m);
        float inv = 1.0f / (ea + eb);
        *reinterpret_cast<float2*>(out + (size_t)gw * 2) = make_float2(ea * inv, eb * inv);
        if (out_size >= 2 * NN * CC)
            *reinterpret_cast<float2*>(out + (size_t)NN * CC + (size_t)gw * 2) =
                make_float2(sx, sy);
    }
}

// ------------------------------------------------------------------ launch
extern "C" void kernel_launch(void* const* d_in, const int* in_sizes, int n_in,
                              void* d_out, int out_size) {
    const float* x  = (const float*)d_in[0];
    const int*   ei = (const int*)d_in[1];
    const int*   et = (const int*)d_in[2];
    const float* W1 = (const float*)d_in[3];
    const float* W2 = (const float*)d_in[4];
    const float* W3 = (const float*)d_in[5];
    float* out = (float*)d_out;

    static int attr_set = 0;
    if (!attr_set) {
        cudaFuncSetAttribute(gemm_kernel,
                             cudaFuncAttributeMaxDynamicSharedMemorySize, 4 * TBYTES);
        attr_set = 1;
    }

    float *p_h1, *p_h2;
    int* p_cnt;
    cudaGetSymbolAddress((void**)&p_h1, g_h1);
    cudaGetSymbolAddress((void**)&p_h2, g_h2);
    cudaGetSymbolAddress((void**)&p_cnt, g_cnt);

    const int gemm_smem = 4 * TBYTES;               // 139264
    const int gemm_grid = (NN + 127) / 128;         // 782
    const int gath_grid = (NN * 32 + 255) / 256;    // 12500

    // counts -> inv(+cursor zero), CSR offsets + placement
    zero_i_kernel<<<(NR + 255) / 256, 256>>>(p_cnt, NR);
    count_kernel<<<(NE + 255) / 256, 256>>>(ei, et);
    inv_kernel<<<(NR + 255) / 256, 256>>>();
    k_blocksum<<<SCAN_NBLK, 256>>>();
    k_scanb<<<1, 32>>>(SCAN_NBLK);
    k_scanlocal<<<SCAN_NBLK, 256>>>();
    place_kernel<<<(NE + 255) / 256, 256>>>(ei, et);

    // weight splits
    convert_w_kernel<<<(RR * DD * DD + 255) / 256, 256>>>(W1, 0);
    convert_w_kernel<<<(RR * DD * DD + 255) / 256, 256>>>(W2, 1);

    // layer 1
    gather_kernel<<<gath_grid, 256>>>(x);
    gemm_kernel<<<gemm_grid, 256, gemm_smem>>>(0, p_h1);

    // layer 2
    gather_kernel<<<gath_grid, 256>>>(p_h1);
    gemm_kernel<<<gemm_grid, 256, gemm_smem>>>(1, p_h2);

    // layer 3: tiny transform then fused CSR-mean + softmax
    transform3_kernel<<<(NN + 31) / 32, 128>>>(p_h2, W3);
    final_kernel<<<gath_grid, 256>>>(out, out_size);
}